// round 12
// baseline (speedup 1.0000x reference)
#include <cuda_runtime.h>
#include <cuda_bf16.h>
#include <cstdint>

#define N_NODES 100000
#define F_DIM   128
#define D_DIM   32
#define L_SEQ   100
#define B_BATCH 1024
#define R_RET   5
#define ROWS_PB 64
#define N_PBLK  ((N_NODES + ROWS_PB - 1) / ROWS_PB)   // 1563

// smem layout for proj (dynamic): bf16 rows, stride 272B -> conflict-free
#define A_STRIDE 272
#define SM_AHI   0
#define SM_ALO   17408            // 64*272
#define SM_WHI   34816
#define SM_WLO   43520            // +32*272
#define SM_DYN   52224            // 4 blocks/SM

__device__ float g_proj[N_NODES * D_DIM];
__device__ int   g_skill[N_NODES];

// pack two f32 -> bf16x2, first arg -> LOW 16 bits
__device__ __forceinline__ uint32_t packbf(float lo, float hi) {
    uint32_t r;
    asm("cvt.rn.bf16x2.f32 %0, %1, %2;" : "=r"(r) : "f"(hi), "f"(lo));
    return r;
}
// m16n8k16 row.col bf16 -> f32 accumulate
__device__ __forceinline__ void mma16816(float* d, const uint32_t* a, const uint32_t* b) {
    asm volatile(
        "mma.sync.aligned.m16n8k16.row.col.f32.bf16.bf16.f32 "
        "{%0,%1,%2,%3}, {%4,%5,%6,%7}, {%8,%9}, {%0,%1,%2,%3};\n"
        : "+f"(d[0]), "+f"(d[1]), "+f"(d[2]), "+f"(d[3])
        : "r"(a[0]), "r"(a[1]), "r"(a[2]), "r"(a[3]), "r"(b[0]), "r"(b[1]));
}

// ---------------------------------------------------------------------------
// Kernel 1: proj via mma.sync bf16 split, 64 rows/block (unchanged from R11).
// ---------------------------------------------------------------------------
__global__ __launch_bounds__(256)
void proj_mma_kernel(const float* __restrict__ raw,
                     const float* __restrict__ Wf,
                     const float* __restrict__ bf)
{
    extern __shared__ char sm[];
    __shared__ float bf_sh[D_DIM];

    const int tid  = threadIdx.x;
    const int warp = tid >> 5;
    const int lane = tid & 31;
    const int rowBase = blockIdx.x * ROWS_PB;

    if (tid < D_DIM) bf_sh[tid] = bf[tid];

    #pragma unroll
    for (int j = 0; j < (F_DIM * D_DIM) / 256; j++) {
        int e = tid + j * 256;
        int k = e >> 5, n = e & 31;
        float x = Wf[e];
        __nv_bfloat16 h = __float2bfloat16(x);
        float hf = __bfloat162float(h);
        __nv_bfloat16 l = __float2bfloat16(x - hf);
        *reinterpret_cast<__nv_bfloat16*>(sm + SM_WHI + n * A_STRIDE + k * 2) = h;
        *reinterpret_cast<__nv_bfloat16*>(sm + SM_WLO + n * A_STRIDE + k * 2) = l;
    }

    #pragma unroll
    for (int j = 0; j < (ROWS_PB * F_DIM / 4) / 256; j++) {
        int i = tid + j * 256;
        int r = i >> 5, c4 = i & 31;
        int gr = rowBase + r;
        float4 v = make_float4(0.f, 0.f, 0.f, 0.f);
        if (gr < N_NODES)
            v = *reinterpret_cast<const float4*>(raw + (size_t)gr * F_DIM + c4 * 4);
        if (c4 == 0 && gr < N_NODES) g_skill[gr] = (int)v.x;

        uint32_t h0 = packbf(v.x, v.y);
        uint32_t h1 = packbf(v.z, v.w);
        float hx = __uint_as_float(h0 << 16);
        float hy = __uint_as_float(h0 & 0xffff0000u);
        float hz = __uint_as_float(h1 << 16);
        float hw = __uint_as_float(h1 & 0xffff0000u);
        uint32_t l0 = packbf(v.x - hx, v.y - hy);
        uint32_t l1 = packbf(v.z - hz, v.w - hw);

        uint32_t off = (uint32_t)r * A_STRIDE + c4 * 8;
        *reinterpret_cast<uint2*>(sm + SM_AHI + off) = make_uint2(h0, h1);
        *reinterpret_cast<uint2*>(sm + SM_ALO + off) = make_uint2(l0, l1);
    }
    __syncthreads();

    const int rg = warp >> 1;
    const int ch = warp & 1;
    const int r0 = rg * 16 + (lane >> 2);
    const int kb = ((lane & 3) * 2) * 2;

    float acc[2][4];
    #pragma unroll
    for (int t = 0; t < 2; t++)
        #pragma unroll
        for (int q = 0; q < 4; q++) acc[t][q] = 0.f;

    #pragma unroll
    for (int s = 0; s < 8; s++) {
        const int kob = s * 32;
        uint32_t ahi[4], alo[4];
        {
            const char* pa = sm + SM_AHI + (uint32_t)r0 * A_STRIDE + kob + kb;
            const char* pb = sm + SM_AHI + (uint32_t)(r0 + 8) * A_STRIDE + kob + kb;
            ahi[0] = *reinterpret_cast<const uint32_t*>(pa);
            ahi[1] = *reinterpret_cast<const uint32_t*>(pb);
            ahi[2] = *reinterpret_cast<const uint32_t*>(pa + 16);
            ahi[3] = *reinterpret_cast<const uint32_t*>(pb + 16);
            const char* qa = sm + SM_ALO + (uint32_t)r0 * A_STRIDE + kob + kb;
            const char* qb = sm + SM_ALO + (uint32_t)(r0 + 8) * A_STRIDE + kob + kb;
            alo[0] = *reinterpret_cast<const uint32_t*>(qa);
            alo[1] = *reinterpret_cast<const uint32_t*>(qb);
            alo[2] = *reinterpret_cast<const uint32_t*>(qa + 16);
            alo[3] = *reinterpret_cast<const uint32_t*>(qb + 16);
        }
        #pragma unroll
        for (int t = 0; t < 2; t++) {
            const int n = ch * 16 + t * 8 + (lane >> 2);
            const char* ph = sm + SM_WHI + (uint32_t)n * A_STRIDE + kob + kb;
            const char* pl = sm + SM_WLO + (uint32_t)n * A_STRIDE + kob + kb;
            uint32_t bh[2], bl[2];
            bh[0] = *reinterpret_cast<const uint32_t*>(ph);
            bh[1] = *reinterpret_cast<const uint32_t*>(ph + 16);
            bl[0] = *reinterpret_cast<const uint32_t*>(pl);
            bl[1] = *reinterpret_cast<const uint32_t*>(pl + 16);
            mma16816(acc[t], ahi, bh);
            mma16816(acc[t], ahi, bl);
            mma16816(acc[t], alo, bh);
        }
    }

    const int rowA = rowBase + r0;
    const int rowB = rowA + 8;
    #pragma unroll
    for (int t = 0; t < 2; t++) {
        const int col = ch * 16 + t * 8 + (lane & 3) * 2;
        const float b0 = bf_sh[col], b1 = bf_sh[col + 1];
        if (rowA < N_NODES)
            *reinterpret_cast<float2*>(g_proj + (size_t)rowA * D_DIM + col)
                = make_float2(acc[t][0] + b0, acc[t][1] + b1);
        if (rowB < N_NODES)
            *reinterpret_cast<float2*>(g_proj + (size_t)rowB * D_DIM + col)
                = make_float2(acc[t][2] + b0, acc[t][3] + b1);
    }
}

// ---------------------------------------------------------------------------
// Kernel 2: monolithic per-batch pipeline, R9 structure, 6 blocks/SM.
// Single-l hist loop (cross-warp TLP covers gather latency at occ 75%).
// ---------------------------------------------------------------------------
__global__ __launch_bounds__(256, 6)
void main_kernel(const int* __restrict__ retrieved_nodes,
                 const int* __restrict__ retrieved_indices,
                 const int* __restrict__ dst_node_ids,
                 const float* __restrict__ w_struct, const float* __restrict__ b_struct,
                 const float* __restrict__ ln_g,    const float* __restrict__ ln_b,
                 const float* __restrict__ W_gcn,   const float* __restrict__ b_gcn,
                 const float* __restrict__ W_out,   const float* __restrict__ b_out,
                 float* __restrict__ out)
{
    __shared__ float hist[L_SEQ][D_DIM];
    __shared__ float xw[L_SEQ][D_DIM];
    __shared__ float partial[8][D_DIM];
    __shared__ float dstfeat[D_DIM];
    __shared__ int   nodes_sh[R_RET][L_SEQ];
    __shared__ int   pidx[R_RET];
    __shared__ int   validsh;
    __shared__ int   curskill;

    const int b = blockIdx.x;
    const int tid = threadIdx.x;
    const int warp = tid >> 5;
    const int lane = tid & 31;

    if (tid < R_RET) pidx[tid] = retrieved_indices[b * R_RET + tid];
    if (tid == 0) {
        validsh = 0;
        curskill = g_skill[dst_node_ids[b]];
    }
    if (tid >= 32 && tid < 64)
        dstfeat[tid - 32] = g_proj[(size_t)dst_node_ids[b] * D_DIM + (tid - 32)];
    __syncthreads();

    if (warp < R_RET) {
        const int* src = retrieved_nodes + (size_t)pidx[warp] * L_SEQ;
        for (int l = lane; l < L_SEQ; l += 32) nodes_sh[warp][l] = src[l];
    }
    __syncthreads();

    if (tid < L_SEQ && nodes_sh[0][tid] > 0) atomicAdd(&validsh, 1);

    const int cs = curskill;
    const float wsl = w_struct[lane], bsl = b_struct[lane];
    const float lgl = ln_g[lane],     lbl = ln_b[lane];

    // ---- hist + LayerNorm: warp per l, 10 independent gathers in flight ----
    for (int l = warp; l < L_SEQ; l += 8) {
        float p0, p1, p2, p3, p4;
        int   q0, q1, q2, q3, q4;
        {
            int n0 = nodes_sh[0][l], n1 = nodes_sh[1][l], n2 = nodes_sh[2][l],
                n3 = nodes_sh[3][l], n4 = nodes_sh[4][l];
            p0 = g_proj[(size_t)n0 * D_DIM + lane];
            p1 = g_proj[(size_t)n1 * D_DIM + lane];
            p2 = g_proj[(size_t)n2 * D_DIM + lane];
            p3 = g_proj[(size_t)n3 * D_DIM + lane];
            p4 = g_proj[(size_t)n4 * D_DIM + lane];
            q0 = g_skill[n0]; q1 = g_skill[n1]; q2 = g_skill[n2];
            q3 = g_skill[n3]; q4 = g_skill[n4];
        }
        float s = p0 + p1 + p2 + p3 + p4;
        int simc = (q0==cs) + (q1==cs) + (q2==cs) + (q3==cs) + (q4==cs);
        float val = s * 0.2f + ((float)simc * 0.2f) * wsl + bsl;

        float s1 = val, s2 = val * val;
        #pragma unroll
        for (int o = 16; o; o >>= 1) {
            s1 += __shfl_xor_sync(0xffffffffu, s1, o);
            s2 += __shfl_xor_sync(0xffffffffu, s2, o);
        }
        float mean = s1 * (1.f / 32.f);
        float var  = s2 * (1.f / 32.f) - mean * mean;
        hist[l][lane] = (val - mean) * rsqrtf(var + 1e-5f) * lgl + lbl;
    }

    // W_gcn column in registers (L2-resident, coalesced)
    float wreg[D_DIM];
    #pragma unroll
    for (int k = 0; k < D_DIM; k++) wreg[k] = W_gcn[k * D_DIM + lane];

    __syncthreads();
    const int valid = validsh;

    // ---- xW = hist @ W_gcn : 8x LDS.128 broadcast + 32 FMA per l ----
    for (int l = warp; l < L_SEQ; l += 8) {
        const float4* hp = reinterpret_cast<const float4*>(hist[l]);
        float acc = 0.f;
        #pragma unroll
        for (int q = 0; q < 8; q++) {
            float4 h = hp[q];
            acc = fmaf(h.x, wreg[4 * q + 0], acc);
            acc = fmaf(h.y, wreg[4 * q + 1], acc);
            acc = fmaf(h.z, wreg[4 * q + 2], acc);
            acc = fmaf(h.w, wreg[4 * q + 3], acc);
        }
        xw[l][lane] = acc;
    }
    __syncthreads();

    // ---- chain GCN + relu + mean pool ----
    const float bgl = b_gcn[lane];
    float pacc = 0.f;
    for (int l = warp; l < L_SEQ; l += 8) {
        float degl = (l >= 1 && l < valid) ? 2.f : 1.f;
        float o = xw[l][lane] / degl;
        if (l >= 1 && l < valid) {
            float degp = (l - 1 >= 1 && (l - 1) < valid) ? 2.f : 1.f;
            o += xw[l - 1][lane] * rsqrtf(degp * degl);
        }
        o += bgl;
        pacc += fmaxf(o, 0.f);
    }
    partial[warp][lane] = pacc;
    __syncthreads();

    if (warp == 0) {
        float p = 0.f;
        #pragma unroll
        for (int w = 0; w < 8; w++) p += partial[w][lane];
        partial[0][lane] = p * (1.f / (float)L_SEQ);
    }
    __syncthreads();

    if (warp == 0) {
        float acc = b_out[lane];
        #pragma unroll
        for (int k = 0; k < D_DIM; k++)
            acc = fmaf(partial[0][k], W_out[k * D_DIM + lane], acc);
        out[b * D_DIM + lane] = acc;
    } else if (warp == 1) {
        float acc = b_out[lane];
        #pragma unroll
        for (int k = 0; k < D_DIM; k++)
            acc = fmaf(dstfeat[k], W_out[k * D_DIM + lane], acc);
        out[B_BATCH * D_DIM + b * D_DIM + lane] = acc;
    }
}

// ---------------------------------------------------------------------------
extern "C" void kernel_launch(void* const* d_in, const int* in_sizes, int n_in,
                              void* d_out, int out_size)
{
    const float* raw      = (const float*)d_in[0];
    const int*   rnodes   = (const int*)  d_in[1];
    const int*   rindices = (const int*)  d_in[2];
    const int*   dst_ids  = (const int*)  d_in[4];
    const float* W_feat   = (const float*)d_in[6];
    const float* b_feat   = (const float*)d_in[7];
    const float* w_struct = (const float*)d_in[8];
    const float* b_struct = (const float*)d_in[9];
    const float* ln_g     = (const float*)d_in[10];
    const float* ln_b     = (const float*)d_in[11];
    const float* W_gcn    = (const float*)d_in[12];
    const float* b_gcn    = (const float*)d_in[13];
    const float* W_out    = (const float*)d_in[14];
    const float* b_out    = (const float*)d_in[15];
    float* out = (float*)d_out;

    static int attr_set = 0;
    if (!attr_set) {
        cudaFuncSetAttribute(proj_mma_kernel,
                             cudaFuncAttributeMaxDynamicSharedMemorySize, SM_DYN);
        attr_set = 1;
    }
    proj_mma_kernel<<<N_PBLK, 256, SM_DYN>>>(raw, W_feat, b_feat);
    main_kernel<<<B_BATCH, 256>>>(rnodes, rindices, dst_ids,
                                  w_struct, b_struct, ln_g, ln_b,
                                  W_gcn, b_gcn, W_out, b_out, out);
}

// round 13
// speedup vs baseline: 1.1640x; 1.1640x over previous
#include <cuda_runtime.h>
#include <cuda_bf16.h>
#include <cstdint>

#define N_NODES 100000
#define F_DIM   128
#define D_DIM   32
#define L_SEQ   100
#define B_BATCH 1024
#define R_RET   5
#define ROWS_PB 64
#define N_PBLK  ((N_NODES + ROWS_PB - 1) / ROWS_PB)   // 1563

// smem layout for proj (dynamic): bf16 rows, stride 272B -> conflict-free
#define A_STRIDE 272
#define SM_AHI   0
#define SM_ALO   17408            // 64*272
#define SM_WHI   34816
#define SM_WLO   43520            // +32*272
#define SM_DYN   52224            // 4 blocks/SM

__device__ float g_proj[N_NODES * D_DIM];
__device__ int   g_skill[N_NODES];

// pack two f32 -> bf16x2, first arg -> LOW 16 bits
__device__ __forceinline__ uint32_t packbf(float lo, float hi) {
    uint32_t r;
    asm("cvt.rn.bf16x2.f32 %0, %1, %2;" : "=r"(r) : "f"(hi), "f"(lo));
    return r;
}
// m16n8k16 row.col bf16 -> f32 accumulate
__device__ __forceinline__ void mma16816(float* d, const uint32_t* a, const uint32_t* b) {
    asm volatile(
        "mma.sync.aligned.m16n8k16.row.col.f32.bf16.bf16.f32 "
        "{%0,%1,%2,%3}, {%4,%5,%6,%7}, {%8,%9}, {%0,%1,%2,%3};\n"
        : "+f"(d[0]), "+f"(d[1]), "+f"(d[2]), "+f"(d[3])
        : "r"(a[0]), "r"(a[1]), "r"(a[2]), "r"(a[3]), "r"(b[0]), "r"(b[1]));
}

// ---------------------------------------------------------------------------
// Kernel 1: proj via mma.sync bf16 split, 64 rows/block (R11 version).
// ---------------------------------------------------------------------------
__global__ __launch_bounds__(256)
void proj_mma_kernel(const float* __restrict__ raw,
                     const float* __restrict__ Wf,
                     const float* __restrict__ bf)
{
    extern __shared__ char sm[];
    __shared__ float bf_sh[D_DIM];

    const int tid  = threadIdx.x;
    const int warp = tid >> 5;
    const int lane = tid & 31;
    const int rowBase = blockIdx.x * ROWS_PB;

    if (tid < D_DIM) bf_sh[tid] = bf[tid];

    #pragma unroll
    for (int j = 0; j < (F_DIM * D_DIM) / 256; j++) {
        int e = tid + j * 256;
        int k = e >> 5, n = e & 31;
        float x = Wf[e];
        __nv_bfloat16 h = __float2bfloat16(x);
        float hf = __bfloat162float(h);
        __nv_bfloat16 l = __float2bfloat16(x - hf);
        *reinterpret_cast<__nv_bfloat16*>(sm + SM_WHI + n * A_STRIDE + k * 2) = h;
        *reinterpret_cast<__nv_bfloat16*>(sm + SM_WLO + n * A_STRIDE + k * 2) = l;
    }

    #pragma unroll
    for (int j = 0; j < (ROWS_PB * F_DIM / 4) / 256; j++) {
        int i = tid + j * 256;
        int r = i >> 5, c4 = i & 31;
        int gr = rowBase + r;
        float4 v = make_float4(0.f, 0.f, 0.f, 0.f);
        if (gr < N_NODES)
            v = *reinterpret_cast<const float4*>(raw + (size_t)gr * F_DIM + c4 * 4);
        if (c4 == 0 && gr < N_NODES) g_skill[gr] = (int)v.x;

        uint32_t h0 = packbf(v.x, v.y);
        uint32_t h1 = packbf(v.z, v.w);
        float hx = __uint_as_float(h0 << 16);
        float hy = __uint_as_float(h0 & 0xffff0000u);
        float hz = __uint_as_float(h1 << 16);
        float hw = __uint_as_float(h1 & 0xffff0000u);
        uint32_t l0 = packbf(v.x - hx, v.y - hy);
        uint32_t l1 = packbf(v.z - hz, v.w - hw);

        uint32_t off = (uint32_t)r * A_STRIDE + c4 * 8;
        *reinterpret_cast<uint2*>(sm + SM_AHI + off) = make_uint2(h0, h1);
        *reinterpret_cast<uint2*>(sm + SM_ALO + off) = make_uint2(l0, l1);
    }
    __syncthreads();

    const int rg = warp >> 1;
    const int ch = warp & 1;
    const int r0 = rg * 16 + (lane >> 2);
    const int kb = ((lane & 3) * 2) * 2;

    float acc[2][4];
    #pragma unroll
    for (int t = 0; t < 2; t++)
        #pragma unroll
        for (int q = 0; q < 4; q++) acc[t][q] = 0.f;

    #pragma unroll
    for (int s = 0; s < 8; s++) {
        const int kob = s * 32;
        uint32_t ahi[4], alo[4];
        {
            const char* pa = sm + SM_AHI + (uint32_t)r0 * A_STRIDE + kob + kb;
            const char* pb = sm + SM_AHI + (uint32_t)(r0 + 8) * A_STRIDE + kob + kb;
            ahi[0] = *reinterpret_cast<const uint32_t*>(pa);
            ahi[1] = *reinterpret_cast<const uint32_t*>(pb);
            ahi[2] = *reinterpret_cast<const uint32_t*>(pa + 16);
            ahi[3] = *reinterpret_cast<const uint32_t*>(pb + 16);
            const char* qa = sm + SM_ALO + (uint32_t)r0 * A_STRIDE + kob + kb;
            const char* qb = sm + SM_ALO + (uint32_t)(r0 + 8) * A_STRIDE + kob + kb;
            alo[0] = *reinterpret_cast<const uint32_t*>(qa);
            alo[1] = *reinterpret_cast<const uint32_t*>(qb);
            alo[2] = *reinterpret_cast<const uint32_t*>(qa + 16);
            alo[3] = *reinterpret_cast<const uint32_t*>(qb + 16);
        }
        #pragma unroll
        for (int t = 0; t < 2; t++) {
            const int n = ch * 16 + t * 8 + (lane >> 2);
            const char* ph = sm + SM_WHI + (uint32_t)n * A_STRIDE + kob + kb;
            const char* pl = sm + SM_WLO + (uint32_t)n * A_STRIDE + kob + kb;
            uint32_t bh[2], bl[2];
            bh[0] = *reinterpret_cast<const uint32_t*>(ph);
            bh[1] = *reinterpret_cast<const uint32_t*>(ph + 16);
            bl[0] = *reinterpret_cast<const uint32_t*>(pl);
            bl[1] = *reinterpret_cast<const uint32_t*>(pl + 16);
            mma16816(acc[t], ahi, bh);
            mma16816(acc[t], ahi, bl);
            mma16816(acc[t], alo, bh);
        }
    }

    const int rowA = rowBase + r0;
    const int rowB = rowA + 8;
    #pragma unroll
    for (int t = 0; t < 2; t++) {
        const int col = ch * 16 + t * 8 + (lane & 3) * 2;
        const float b0 = bf_sh[col], b1 = bf_sh[col + 1];
        if (rowA < N_NODES)
            *reinterpret_cast<float2*>(g_proj + (size_t)rowA * D_DIM + col)
                = make_float2(acc[t][0] + b0, acc[t][1] + b1);
        if (rowB < N_NODES)
            *reinterpret_cast<float2*>(g_proj + (size_t)rowB * D_DIM + col)
                = make_float2(acc[t][2] + b0, acc[t][3] + b1);
    }
}

// ---------------------------------------------------------------------------
// Kernel 2: per-batch pipeline, R9 phase structure, 128-thread blocks
// (4 warps) -> ~8 blocks/SM -> 1024 blocks in ~0.9 waves, no tail.
// ---------------------------------------------------------------------------
#define NW 4
__global__ __launch_bounds__(128)
void main_kernel(const int* __restrict__ retrieved_nodes,
                 const int* __restrict__ retrieved_indices,
                 const int* __restrict__ dst_node_ids,
                 const float* __restrict__ w_struct, const float* __restrict__ b_struct,
                 const float* __restrict__ ln_g,    const float* __restrict__ ln_b,
                 const float* __restrict__ W_gcn,   const float* __restrict__ b_gcn,
                 const float* __restrict__ W_out,   const float* __restrict__ b_out,
                 float* __restrict__ out)
{
    __shared__ float hist[L_SEQ][D_DIM];
    __shared__ float xw[L_SEQ][D_DIM];
    __shared__ float partial[NW][D_DIM];
    __shared__ float dstfeat[D_DIM];
    __shared__ int   nodes_sh[R_RET][L_SEQ];
    __shared__ int   pidx[R_RET];
    __shared__ int   validsh;
    __shared__ int   curskill;

    const int b = blockIdx.x;
    const int tid = threadIdx.x;
    const int warp = tid >> 5;
    const int lane = tid & 31;

    if (tid < R_RET) pidx[tid] = retrieved_indices[b * R_RET + tid];
    if (tid == 0) {
        validsh = 0;
        curskill = g_skill[dst_node_ids[b]];
    }
    if (tid >= 32 && tid < 64)
        dstfeat[tid - 32] = g_proj[(size_t)dst_node_ids[b] * D_DIM + (tid - 32)];
    __syncthreads();

    // node ids: warp r loads row r; warp 0 also loads row 4 (R_RET=5, NW=4)
    {
        for (int r = warp; r < R_RET; r += NW) {
            const int* src = retrieved_nodes + (size_t)pidx[r] * L_SEQ;
            for (int l = lane; l < L_SEQ; l += 32) nodes_sh[r][l] = src[l];
        }
    }
    __syncthreads();

    if (tid < L_SEQ && nodes_sh[0][tid] > 0) atomicAdd(&validsh, 1);

    const int cs = curskill;
    const float wsl = w_struct[lane], bsl = b_struct[lane];
    const float lgl = ln_g[lane],     lbl = ln_b[lane];

    auto layernorm = [&](float val) -> float {
        float s1 = val, s2 = val * val;
        #pragma unroll
        for (int o = 16; o; o >>= 1) {
            s1 += __shfl_xor_sync(0xffffffffu, s1, o);
            s2 += __shfl_xor_sync(0xffffffffu, s2, o);
        }
        float mean = s1 * (1.f / 32.f);
        float var  = s2 * (1.f / 32.f) - mean * mean;
        return (val - mean) * rsqrtf(var + 1e-5f) * lgl + lbl;
    };

    // ---- hist + LayerNorm: warp per l, 2 l in flight (20 gathers) ----
    for (int l0 = warp; l0 < L_SEQ; l0 += 2 * NW) {
        const int l1 = l0 + NW;
        const bool has1 = (l1 < L_SEQ);

        float p0[R_RET], p1[R_RET];
        int   s0[R_RET], s1i[R_RET];
        #pragma unroll
        for (int r = 0; r < R_RET; r++) {
            int n = nodes_sh[r][l0];
            p0[r] = g_proj[(size_t)n * D_DIM + lane];
            s0[r] = g_skill[n];
        }
        if (has1) {
            #pragma unroll
            for (int r = 0; r < R_RET; r++) {
                int n = nodes_sh[r][l1];
                p1[r] = g_proj[(size_t)n * D_DIM + lane];
                s1i[r] = g_skill[n];
            }
        }
        {
            float s = p0[0] + p0[1] + p0[2] + p0[3] + p0[4];
            int simc = (s0[0]==cs) + (s0[1]==cs) + (s0[2]==cs) + (s0[3]==cs) + (s0[4]==cs);
            float val = s * 0.2f + ((float)simc * 0.2f) * wsl + bsl;
            hist[l0][lane] = layernorm(val);
        }
        if (has1) {
            float s = p1[0] + p1[1] + p1[2] + p1[3] + p1[4];
            int simc = (s1i[0]==cs) + (s1i[1]==cs) + (s1i[2]==cs) + (s1i[3]==cs) + (s1i[4]==cs);
            float val = s * 0.2f + ((float)simc * 0.2f) * wsl + bsl;
            hist[l1][lane] = layernorm(val);
        }
    }

    // W_gcn column in registers (L2-resident, coalesced)
    float wreg[D_DIM];
    #pragma unroll
    for (int k = 0; k < D_DIM; k++) wreg[k] = W_gcn[k * D_DIM + lane];

    __syncthreads();
    const int valid = validsh;

    // ---- xW = hist @ W_gcn : 8x LDS.128 broadcast + 32 FMA per l ----
    for (int l = warp; l < L_SEQ; l += NW) {
        const float4* hp = reinterpret_cast<const float4*>(hist[l]);
        float acc = 0.f;
        #pragma unroll
        for (int q = 0; q < 8; q++) {
            float4 h = hp[q];
            acc = fmaf(h.x, wreg[4 * q + 0], acc);
            acc = fmaf(h.y, wreg[4 * q + 1], acc);
            acc = fmaf(h.z, wreg[4 * q + 2], acc);
            acc = fmaf(h.w, wreg[4 * q + 3], acc);
        }
        xw[l][lane] = acc;
    }
    __syncthreads();

    // ---- chain GCN + relu + mean pool ----
    const float bgl = b_gcn[lane];
    float pacc = 0.f;
    for (int l = warp; l < L_SEQ; l += NW) {
        float degl = (l >= 1 && l < valid) ? 2.f : 1.f;
        float o = xw[l][lane] / degl;
        if (l >= 1 && l < valid) {
            float degp = (l - 1 >= 1 && (l - 1) < valid) ? 2.f : 1.f;
            o += xw[l - 1][lane] * rsqrtf(degp * degl);
        }
        o += bgl;
        pacc += fmaxf(o, 0.f);
    }
    partial[warp][lane] = pacc;
    __syncthreads();

    if (warp == 0) {
        float p = 0.f;
        #pragma unroll
        for (int w = 0; w < NW; w++) p += partial[w][lane];
        partial[0][lane] = p * (1.f / (float)L_SEQ);
    }
    __syncthreads();

    if (warp == 0) {
        float acc = b_out[lane];
        #pragma unroll
        for (int k = 0; k < D_DIM; k++)
            acc = fmaf(partial[0][k], W_out[k * D_DIM + lane], acc);
        out[b * D_DIM + lane] = acc;
    } else if (warp == 1) {
        float acc = b_out[lane];
        #pragma unroll
        for (int k = 0; k < D_DIM; k++)
            acc = fmaf(dstfeat[k], W_out[k * D_DIM + lane], acc);
        out[B_BATCH * D_DIM + b * D_DIM + lane] = acc;
    }
}

// ---------------------------------------------------------------------------
extern "C" void kernel_launch(void* const* d_in, const int* in_sizes, int n_in,
                              void* d_out, int out_size)
{
    const float* raw      = (const float*)d_in[0];
    const int*   rnodes   = (const int*)  d_in[1];
    const int*   rindices = (const int*)  d_in[2];
    const int*   dst_ids  = (const int*)  d_in[4];
    const float* W_feat   = (const float*)d_in[6];
    const float* b_feat   = (const float*)d_in[7];
    const float* w_struct = (const float*)d_in[8];
    const float* b_struct = (const float*)d_in[9];
    const float* ln_g     = (const float*)d_in[10];
    const float* ln_b     = (const float*)d_in[11];
    const float* W_gcn    = (const float*)d_in[12];
    const float* b_gcn    = (const float*)d_in[13];
    const float* W_out    = (const float*)d_in[14];
    const float* b_out    = (const float*)d_in[15];
    float* out = (float*)d_out;

    static int attr_set = 0;
    if (!attr_set) {
        cudaFuncSetAttribute(proj_mma_kernel,
                             cudaFuncAttributeMaxDynamicSharedMemorySize, SM_DYN);
        attr_set = 1;
    }
    proj_mma_kernel<<<N_PBLK, 256, SM_DYN>>>(raw, W_feat, b_feat);
    main_kernel<<<B_BATCH, 128>>>(rnodes, rindices, dst_ids,
                                  w_struct, b_struct, ln_g, ln_b,
                                  W_gcn, b_gcn, W_out, b_out, out);
}